// round 2
// baseline (speedup 1.0000x reference)
#include <cuda_runtime.h>
#include <cuda_bf16.h>

// out[n, j] = x[n, j] + (1/512) * sum_{k=512..1023} x[n, k]
// x: [131072, 1024] f32, out: [131072, 512] f32
//
// One WARP per row (no __syncthreads, no smem):
//   each lane loads 4 tail float4 + 4 head float4 (MLP=8, front-batched),
//   warp shfl reduce, add mean, store 4 float4.
// 256-thread blocks -> 8 rows/block -> 16384 blocks.

static constexpr int ROW_IN  = 1024;
static constexpr int ROW_OUT = 512;
static constexpr int THREADS = 256;
static constexpr int ROWS_PER_BLOCK = THREADS / 32;

__global__ __launch_bounds__(THREADS)
void projection_kernel(const float* __restrict__ x,
                       float* __restrict__ out,
                       int n_rows)
{
    int warp = threadIdx.x >> 5;
    int lane = threadIdx.x & 31;
    int row  = blockIdx.x * ROWS_PER_BLOCK + warp;
    if (row >= n_rows) return;

    const float4* xrow = reinterpret_cast<const float4*>(x + (size_t)row * ROW_IN);
    float4*       orow = reinterpret_cast<float4*>(out + (size_t)row * ROW_OUT);

    // ---- front-batch all 8 loads (tail first: they feed the reduction) ----
    // tail: float4 indices [128, 256)
    float4 t0 = __ldcs(&xrow[128 + lane]);
    float4 t1 = __ldcs(&xrow[160 + lane]);
    float4 t2 = __ldcs(&xrow[192 + lane]);
    float4 t3 = __ldcs(&xrow[224 + lane]);
    // head: float4 indices [0, 128)
    float4 h0 = __ldcs(&xrow[      lane]);
    float4 h1 = __ldcs(&xrow[ 32 + lane]);
    float4 h2 = __ldcs(&xrow[ 64 + lane]);
    float4 h3 = __ldcs(&xrow[ 96 + lane]);

    float s = (t0.x + t0.y) + (t0.z + t0.w)
            + (t1.x + t1.y) + (t1.z + t1.w)
            + (t2.x + t2.y) + (t2.z + t2.w)
            + (t3.x + t3.y) + (t3.z + t3.w);

    #pragma unroll
    for (int off = 16; off > 0; off >>= 1)
        s += __shfl_xor_sync(0xFFFFFFFFu, s, off);

    float mean = s * (1.0f / 512.0f);

    h0.x += mean; h0.y += mean; h0.z += mean; h0.w += mean;
    h1.x += mean; h1.y += mean; h1.z += mean; h1.w += mean;
    h2.x += mean; h2.y += mean; h2.z += mean; h2.w += mean;
    h3.x += mean; h3.y += mean; h3.z += mean; h3.w += mean;

    orow[      lane] = h0;
    orow[ 32 + lane] = h1;
    orow[ 64 + lane] = h2;
    orow[ 96 + lane] = h3;
}

extern "C" void kernel_launch(void* const* d_in, const int* in_sizes, int n_in,
                              void* d_out, int out_size)
{
    const float* x = (const float*)d_in[0];
    float* out = (float*)d_out;

    int n_rows = in_sizes[0] / ROW_IN;  // 131072
    int blocks = (n_rows + ROWS_PER_BLOCK - 1) / ROWS_PER_BLOCK;

    projection_kernel<<<blocks, THREADS>>>(x, out, n_rows);
}

// round 3
// speedup vs baseline: 1.0388x; 1.0388x over previous
#include <cuda_runtime.h>
#include <cuda_bf16.h>

// out[n, j] = x[n, j] + (1/512) * sum_{k=512..1023} x[n, k]
// x: [131072, 1024] f32, out: [131072, 512] f32
//
// 256-thread block handles 2 rows (128 threads each), one shared barrier.
// Per thread: 1 tail float4 + 1 head float4 (MLP_p1=2 -> low L1tex queue
// contention), warp shfl reduce -> smem partials -> broadcast add -> store.
// Streaming cache hints (.cs) on all global traffic: zero reuse workload.

static constexpr int ROW_IN  = 1024;
static constexpr int ROW_OUT = 512;
static constexpr int THREADS = 256;              // 2 rows x 128 threads

__global__ __launch_bounds__(THREADS)
void projection_kernel(const float* __restrict__ x,
                       float* __restrict__ out)
{
    // sub-block: which of the 2 rows this thread works on
    int sub  = threadIdx.x >> 7;                  // 0 or 1
    int tid  = threadIdx.x & 127;                 // 0..127 within row
    int lane = threadIdx.x & 31;
    int warp = (threadIdx.x >> 5) & 3;            // warp within sub-block

    size_t row = (size_t)blockIdx.x * 2 + sub;

    const float4* xrow = reinterpret_cast<const float4*>(x + row * ROW_IN);
    float4*       orow = reinterpret_cast<float4*>(out + row * ROW_OUT);

    // ---- front-batch both loads (MLP_p1 = 2) ----
    float4 t = __ldcs(&xrow[128 + tid]);   // tail: feeds reduction
    float4 h = __ldcs(&xrow[tid]);         // head: held for the add

    float s = (t.x + t.y) + (t.z + t.w);

    #pragma unroll
    for (int off = 16; off > 0; off >>= 1)
        s += __shfl_xor_sync(0xFFFFFFFFu, s, off);

    __shared__ float partial[8];           // 4 warps x 2 rows
    if (lane == 0) partial[sub * 4 + warp] = s;
    __syncthreads();

    float total = (partial[sub * 4 + 0] + partial[sub * 4 + 1])
                + (partial[sub * 4 + 2] + partial[sub * 4 + 3]);
    float mean = total * (1.0f / 512.0f);

    h.x += mean; h.y += mean; h.z += mean; h.w += mean;

    __stcs(&orow[tid], h);
}

extern "C" void kernel_launch(void* const* d_in, const int* in_sizes, int n_in,
                              void* d_out, int out_size)
{
    const float* x = (const float*)d_in[0];
    float* out = (float*)d_out;

    int n_rows = in_sizes[0] / ROW_IN;     // 131072, even
    int blocks = n_rows / 2;               // 65536

    projection_kernel<<<blocks, THREADS>>>(x, out);
}